// round 4
// baseline (speedup 1.0000x reference)
#include <cuda_runtime.h>
#include <cstdint>

typedef unsigned long long ull;

// Problem constants
#define TT 512
#define DD 2048
#define FFDIM 768
#define EE 128
#define KSEL 8

// -------- scratch (device globals; no allocation allowed) --------
__device__ int   g_cnt[EE];
__device__ int   g_list[EE * TT];              // packed token*8+slot, per expert
__device__ float g_wt[TT * KSEL];              // combine weight per (token,slot)
__device__ float g_H[TT * KSEL * FFDIM];       // 12.6 MB intermediate (pre-scaled by weight)
__device__ float g_P[TT * KSEL * DD];          // 33.5 MB partial outputs per (token,slot)

// -------- packed f32x2 helpers --------
__device__ __forceinline__ ull pack2(float lo, float hi) {
    ull r;
    asm("mov.b64 %0, {%1, %2};" : "=l"(r) : "f"(lo), "f"(hi));
    return r;
}
__device__ __forceinline__ void unpack2(ull v, float& lo, float& hi) {
    asm("mov.b64 {%0, %1}, %2;" : "=f"(lo), "=f"(hi) : "l"(v));
}
__device__ __forceinline__ void fma2(ull& d, ull a, ull b) {
    asm("fma.rn.f32x2 %0, %1, %2, %0;" : "+l"(d) : "l"(a), "l"(b));
}

// -------- cp.async helpers --------
__device__ __forceinline__ unsigned smem_u32(const void* p) {
    return (unsigned)__cvta_generic_to_shared(p);
}
__device__ __forceinline__ void cp16(unsigned s, const void* g) {
    asm volatile("cp.async.cg.shared.global [%0], [%1], 16;" :: "r"(s), "l"(g));
}
#define CP_COMMIT asm volatile("cp.async.commit_group;")
#define CP_WAIT1  asm volatile("cp.async.wait_group 1;")

#define APAD 36   // padded m-stride for transposed A tile

// ---------------------------------------------------------------
__global__ void zero_cnt_kernel() {
    if (threadIdx.x < EE) g_cnt[threadIdx.x] = 0;
}

// ---------------------------------------------------------------
// Router: 1 block per token, 128 threads (one per expert).
__global__ __launch_bounds__(128) void router_kernel(
    const float* __restrict__ x, const float* __restrict__ wg) {
    __shared__ float xs[DD];
    __shared__ float logit[EE];
    __shared__ float red[EE];
    __shared__ int   redi[EE];
    __shared__ float tv[KSEL];
    __shared__ int   ti[KSEL];

    const int t = blockIdx.x;
    const int tid = threadIdx.x;

    const float4* xr = reinterpret_cast<const float4*>(x + (size_t)t * DD);
    float4* xs4 = reinterpret_cast<float4*>(xs);
    for (int i = tid; i < DD / 4; i += 128) xs4[i] = xr[i];
    __syncthreads();

    float acc = 0.f;
#pragma unroll 8
    for (int d = 0; d < DD; d++) acc += xs[d] * wg[d * EE + tid];
    logit[tid] = acc;
    __syncthreads();

    for (int k = 0; k < KSEL; k++) {
        red[tid] = logit[tid];
        redi[tid] = tid;
        __syncthreads();
        for (int s = 64; s > 0; s >>= 1) {
            if (tid < s) {
                if (red[tid + s] > red[tid]) {
                    red[tid] = red[tid + s];
                    redi[tid] = redi[tid + s];
                }
            }
            __syncthreads();
        }
        if (tid == 0) {
            tv[k] = red[0];
            ti[k] = redi[0];
            logit[redi[0]] = -1e30f;
        }
        __syncthreads();
    }

    if (tid < KSEL) red[tid] = __expf(tv[tid] - tv[0]);
    __syncthreads();
    if (tid == 0) {
        float s = 0.f;
        for (int k = 0; k < KSEL; k++) s += red[k];
        float inv = 1.f / s;
        for (int k = 0; k < KSEL; k++) {
            int e = ti[k];
            g_wt[t * KSEL + k] = red[k] * inv;
            int pos = atomicAdd(&g_cnt[e], 1);
            g_list[e * TT + pos] = t * KSEL + k;
        }
    }
}

// ---------------------------------------------------------------
// Gate+Up grouped GEMM: BM=32, BN=128 per matrix, BK=16.
// grid (FF/128=6, 16, 128), block 256, static smem ~37 KB, occ 2.
__global__ void __launch_bounds__(256, 2) gateup_kernel(
    const float* __restrict__ x,
    const float* __restrict__ wgp,
    const float* __restrict__ wup) {
    const int e = blockIdx.z;
    const int Mi = g_cnt[e];
    const int m0 = blockIdx.y * 32;
    if (m0 >= Mi) return;
    const int n0 = blockIdx.x * 128;
    const int tid = threadIdx.x;
    const int tidy = tid >> 6;      // 0..3
    const int tidx = tid & 63;      // 0..63

    __shared__ float As[2][16][APAD];   // transposed A: [k][m], padded
    __shared__ float Gs[2][16][128];
    __shared__ float Us[2][16][128];
    __shared__ int   s_ts[32];
    __shared__ int   s_tok[32];
    __shared__ float s_w[32];

    if (tid < 32) {
        int mi = m0 + tid;
        int cl = (mi < Mi) ? mi : (Mi - 1);
        int ts = g_list[e * TT + cl];
        s_ts[tid] = ts;
        s_tok[tid] = ts >> 3;
        s_w[tid] = g_wt[ts];
    }
    __syncthreads();

    // A staging: threads 0..127, m = tid>>2, kq = tid&3 (float4 along k)
    const int am = tid >> 2;
    const int akq = tid & 3;
    const float* a_src = (tid < 128) ? (x + (size_t)s_tok[am] * DD + akq * 4) : x;
    const size_t gbase = (size_t)e * DD * FFDIM + n0;

    float4 rA = *(const float4*)(a_src);
    // B tile 0 -> buf 0 : 16x128 = 512 float4, 2 per thread per matrix
#pragma unroll
    for (int i = 0; i < 2; i++) {
        int c = tid + i * 256;
        int row = c >> 5, col = c & 31;
        size_t off = gbase + (size_t)row * FFDIM + col * 4;
        cp16(smem_u32(&Gs[0][row][col * 4]), wgp + off);
        cp16(smem_u32(&Us[0][row][col * 4]), wup + off);
    }
    CP_COMMIT;
    if (tid < 128) {
#pragma unroll
        for (int j = 0; j < 4; j++) As[0][akq * 4 + j][am] = ((float*)&rA)[j];
        rA = *(const float4*)(a_src + 16);
    }
#pragma unroll
    for (int i = 0; i < 2; i++) {
        int c = tid + i * 256;
        int row = c >> 5, col = c & 31;
        size_t off = gbase + (size_t)(16 + row) * FFDIM + col * 4;
        cp16(smem_u32(&Gs[1][row][col * 4]), wgp + off);
        cp16(smem_u32(&Us[1][row][col * 4]), wup + off);
    }
    CP_COMMIT;
    CP_WAIT1;
    __syncthreads();

    ull accg[8][2] = {};
    ull accu[8][2] = {};
    const int mb = tidy * 8;

    const int NT = DD / 16;   // 128
    for (int t = 0; t < NT; t++) {
        const int buf = t & 1;
        if (tid < 128 && t + 1 < NT) {
#pragma unroll
            for (int j = 0; j < 4; j++) As[buf ^ 1][akq * 4 + j][am] = ((float*)&rA)[j];
        }

#pragma unroll 2
        for (int kp = 0; kp < 8; kp++) {
            float4 ae0 = *(const float4*)(&As[buf][2 * kp][mb]);
            float4 ae1 = *(const float4*)(&As[buf][2 * kp][mb + 4]);
            float4 ao0 = *(const float4*)(&As[buf][2 * kp + 1][mb]);
            float4 ao1 = *(const float4*)(&As[buf][2 * kp + 1][mb + 4]);
            ull a[8];
            a[0] = pack2(ae0.x, ao0.x); a[1] = pack2(ae0.y, ao0.y);
            a[2] = pack2(ae0.z, ao0.z); a[3] = pack2(ae0.w, ao0.w);
            a[4] = pack2(ae1.x, ao1.x); a[5] = pack2(ae1.y, ao1.y);
            a[6] = pack2(ae1.z, ao1.z); a[7] = pack2(ae1.w, ao1.w);
            float2 g0 = *(const float2*)(&Gs[buf][2 * kp][tidx * 2]);
            float2 g1 = *(const float2*)(&Gs[buf][2 * kp + 1][tidx * 2]);
            float2 u0 = *(const float2*)(&Us[buf][2 * kp][tidx * 2]);
            float2 u1 = *(const float2*)(&Us[buf][2 * kp + 1][tidx * 2]);
            ull bg0 = pack2(g0.x, g1.x), bg1 = pack2(g0.y, g1.y);
            ull bu0 = pack2(u0.x, u1.x), bu1 = pack2(u0.y, u1.y);
#pragma unroll
            for (int i = 0; i < 8; i++) {
                fma2(accg[i][0], a[i], bg0);
                fma2(accg[i][1], a[i], bg1);
                fma2(accu[i][0], a[i], bu0);
                fma2(accu[i][1], a[i], bu1);
            }
        }
        __syncthreads();
        if (t + 2 < NT) {
            if (tid < 128) rA = *(const float4*)(a_src + (t + 2) * 16);
#pragma unroll
            for (int i = 0; i < 2; i++) {
                int c = tid + i * 256;
                int row = c >> 5, col = c & 31;
                size_t off = gbase + (size_t)((t + 2) * 16 + row) * FFDIM + col * 4;
                cp16(smem_u32(&Gs[buf][row][col * 4]), wgp + off);
                cp16(smem_u32(&Us[buf][row][col * 4]), wup + off);
            }
        }
        CP_COMMIT;
        CP_WAIT1;
        __syncthreads();
    }

    // epilogue: h = w * silu(g) * u  (float2 per thread per row)
#pragma unroll
    for (int i = 0; i < 8; i++) {
        int r = mb + i;
        if (m0 + r < Mi) {
            float w = s_w[r];
            float2 hv;
            float gl, gh, ul, uh;
            unpack2(accg[i][0], gl, gh);
            unpack2(accu[i][0], ul, uh);
            float g = gl + gh, u = ul + uh;
            hv.x = w * u * g / (1.f + __expf(-g));
            unpack2(accg[i][1], gl, gh);
            unpack2(accu[i][1], ul, uh);
            g = gl + gh; u = ul + uh;
            hv.y = w * u * g / (1.f + __expf(-g));
            *(float2*)(g_H + (size_t)s_ts[r] * FFDIM + n0 + tidx * 2) = hv;
        }
    }
}

// ---------------------------------------------------------------
// Down grouped GEMM: BM=32, BN=256, BK=16.
// grid (D/256=8, 16, 128), block 256, static smem ~37 KB, occ 2.
__global__ void __launch_bounds__(256, 2) down_kernel(const float* __restrict__ wdp) {
    const int e = blockIdx.z;
    const int Mi = g_cnt[e];
    const int m0 = blockIdx.y * 32;
    if (m0 >= Mi) return;
    const int n0 = blockIdx.x * 256;
    const int tid = threadIdx.x;
    const int tidy = tid >> 6;
    const int tidx = tid & 63;

    __shared__ float As[2][16][APAD];
    __shared__ float Bs[2][16][256];
    __shared__ int   s_ts[32];

    if (tid < 32) {
        int mi = m0 + tid;
        int cl = (mi < Mi) ? mi : (Mi - 1);
        s_ts[tid] = g_list[e * TT + cl];
    }
    __syncthreads();

    const int am = tid >> 2;
    const int akq = tid & 3;
    const float* a_src = (tid < 128) ? (g_H + (size_t)s_ts[am] * FFDIM + akq * 4) : g_H;
    const size_t bbase = (size_t)e * FFDIM * DD + n0;

    float4 rA = *(const float4*)(a_src);
    // B tile 0: 16x256 = 1024 float4, 4 per thread
#pragma unroll
    for (int i = 0; i < 4; i++) {
        int c = tid + i * 256;
        int row = c >> 6, col = c & 63;
        cp16(smem_u32(&Bs[0][row][col * 4]), wdp + bbase + (size_t)row * DD + col * 4);
    }
    CP_COMMIT;
    if (tid < 128) {
#pragma unroll
        for (int j = 0; j < 4; j++) As[0][akq * 4 + j][am] = ((float*)&rA)[j];
        rA = *(const float4*)(a_src + 16);
    }
#pragma unroll
    for (int i = 0; i < 4; i++) {
        int c = tid + i * 256;
        int row = c >> 6, col = c & 63;
        cp16(smem_u32(&Bs[1][row][col * 4]), wdp + bbase + (size_t)(16 + row) * DD + col * 4);
    }
    CP_COMMIT;
    CP_WAIT1;
    __syncthreads();

    ull acc[8][4] = {};
    const int mb = tidy * 8;

    const int NT = FFDIM / 16;   // 48
    for (int t = 0; t < NT; t++) {
        const int buf = t & 1;
        if (tid < 128 && t + 1 < NT) {
#pragma unroll
            for (int j = 0; j < 4; j++) As[buf ^ 1][akq * 4 + j][am] = ((float*)&rA)[j];
        }

#pragma unroll 2
        for (int kp = 0; kp < 8; kp++) {
            float4 ae0 = *(const float4*)(&As[buf][2 * kp][mb]);
            float4 ae1 = *(const float4*)(&As[buf][2 * kp][mb + 4]);
            float4 ao0 = *(const float4*)(&As[buf][2 * kp + 1][mb]);
            float4 ao1 = *(const float4*)(&As[buf][2 * kp + 1][mb + 4]);
            ull a[8];
            a[0] = pack2(ae0.x, ao0.x); a[1] = pack2(ae0.y, ao0.y);
            a[2] = pack2(ae0.z, ao0.z); a[3] = pack2(ae0.w, ao0.w);
            a[4] = pack2(ae1.x, ao1.x); a[5] = pack2(ae1.y, ao1.y);
            a[6] = pack2(ae1.z, ao1.z); a[7] = pack2(ae1.w, ao1.w);
            float4 b0 = *(const float4*)(&Bs[buf][2 * kp][tidx * 4]);
            float4 b1 = *(const float4*)(&Bs[buf][2 * kp + 1][tidx * 4]);
            ull bb[4] = {pack2(b0.x, b1.x), pack2(b0.y, b1.y),
                         pack2(b0.z, b1.z), pack2(b0.w, b1.w)};
#pragma unroll
            for (int i = 0; i < 8; i++) {
#pragma unroll
                for (int j = 0; j < 4; j++) {
                    fma2(acc[i][j], a[i], bb[j]);
                }
            }
        }
        __syncthreads();
        if (t + 2 < NT) {
            if (tid < 128) rA = *(const float4*)(a_src + (t + 2) * 16);
#pragma unroll
            for (int i = 0; i < 4; i++) {
                int c = tid + i * 256;
                int row = c >> 6, col = c & 63;
                size_t off = bbase + (size_t)((t + 2) * 16 + row) * DD + col * 4;
                cp16(smem_u32(&Bs[buf][row][col * 4]), wdp + off);
            }
        }
        CP_COMMIT;
        CP_WAIT1;
        __syncthreads();
    }

#pragma unroll
    for (int i = 0; i < 8; i++) {
        int r = mb + i;
        if (m0 + r < Mi) {
            float4 v;
            float lo, hi;
            unpack2(acc[i][0], lo, hi); v.x = lo + hi;
            unpack2(acc[i][1], lo, hi); v.y = lo + hi;
            unpack2(acc[i][2], lo, hi); v.z = lo + hi;
            unpack2(acc[i][3], lo, hi); v.w = lo + hi;
            *(float4*)(g_P + (size_t)s_ts[r] * DD + n0 + tidx * 4) = v;
        }
    }
}

// ---------------------------------------------------------------
__global__ __launch_bounds__(256) void combine_kernel(float* __restrict__ out) {
    int idx = blockIdx.x * blockDim.x + threadIdx.x;   // over T*D/4
    int t = idx / (DD / 4);
    int d4 = idx % (DD / 4);
    const float4* p = reinterpret_cast<const float4*>(g_P);
    float4 s = make_float4(0.f, 0.f, 0.f, 0.f);
#pragma unroll
    for (int k = 0; k < KSEL; k++) {
        float4 v = p[((size_t)(t * KSEL + k)) * (DD / 4) + d4];
        s.x += v.x; s.y += v.y; s.z += v.z; s.w += v.w;
    }
    reinterpret_cast<float4*>(out)[idx] = s;
}

// ---------------------------------------------------------------
extern "C" void kernel_launch(void* const* d_in, const int* in_sizes, int n_in,
                              void* d_out, int out_size) {
    const float* x   = (const float*)d_in[0];   // [T, D]
    const float* wg  = (const float*)d_in[1];   // [D, E]
    const float* wgp = (const float*)d_in[2];   // [E, D, FF]
    const float* wup = (const float*)d_in[3];   // [E, D, FF]
    const float* wdp = (const float*)d_in[4];   // [E, FF, D]
    float* out = (float*)d_out;                 // [T, D]

    zero_cnt_kernel<<<1, 128>>>();
    router_kernel<<<TT, 128>>>(x, wg);

    dim3 g1(FFDIM / 128, 16, EE);               // (6, 16, 128)
    gateup_kernel<<<g1, 256>>>(x, wgp, wup);

    dim3 g2(DD / 256, 16, EE);                  // (8, 16, 128)
    down_kernel<<<g2, 256>>>(wdp);

    combine_kernel<<<(TT * DD / 4) / 256, 256>>>(out);
}